// round 8
// baseline (speedup 1.0000x reference)
#include <cuda_runtime.h>
#include <cuda_bf16.h>
#include <cstdint>

// Problem constants (fixed by the dataset)
#define BB 32      // batch
#define LL 128     // sequence length
#define TT 63      // tree nodes (2^6 - 1)
#define EE 128     // embedding dim
#define CC 128     // conv/encoder channels
#define HH 256     // GRU hidden
#define GG 768     // 3*H gate columns

// ---------------------------------------------------------------------------
// f32x2 helpers (kept for K2)
// ---------------------------------------------------------------------------
__device__ __forceinline__ unsigned long long fma2(unsigned long long a,
                                                   unsigned long long b,
                                                   unsigned long long c) {
    unsigned long long d;
    asm("fma.rn.f32x2 %0, %1, %2, %3;" : "=l"(d) : "l"(a), "l"(b), "l"(c));
    return d;
}
__device__ __forceinline__ unsigned long long pk2(float v) {
    unsigned long long r;
    asm("mov.b64 %0, {%1, %1};" : "=l"(r) : "f"(v));
    return r;
}
__device__ __forceinline__ float2 upk(unsigned long long v) {
    float2 f;
    asm("mov.b64 {%0, %1}, %2;" : "=f"(f.x), "=f"(f.y) : "l"(v));
    return f;
}

__device__ __forceinline__ uint32_t smem_u32(const void* p) {
    uint32_t a;
    asm("{ .reg .u64 t; cvta.to.shared.u64 t, %1; cvt.u32.u64 %0, t; }"
        : "=r"(a) : "l"(p));
    return a;
}

// ldmatrix x4 (sm_75+; compiles at plain sm_100)
__device__ __forceinline__ void ldsm_x4(uint32_t& r0, uint32_t& r1,
                                        uint32_t& r2, uint32_t& r3, uint32_t addr) {
    asm volatile("ldmatrix.sync.aligned.m8n8.x4.shared.b16 {%0,%1,%2,%3}, [%4];"
                 : "=r"(r0), "=r"(r1), "=r"(r2), "=r"(r3) : "r"(addr));
}
// bf16 HMMA m16n8k16 (sm_80+)
__device__ __forceinline__ void hmma(float& d0, float& d1, float& d2, float& d3,
                                     uint32_t a0, uint32_t a1, uint32_t a2, uint32_t a3,
                                     uint32_t b0, uint32_t b1) {
    asm volatile("mma.sync.aligned.m16n8k16.row.col.f32.bf16.bf16.f32 "
                 "{%0,%1,%2,%3}, {%4,%5,%6,%7}, {%8,%9}, {%0,%1,%2,%3};"
                 : "+f"(d0), "+f"(d1), "+f"(d2), "+f"(d3)
                 : "r"(a0), "r"(a1), "r"(a2), "r"(a3), "r"(b0), "r"(b1));
}

// ---------------------------------------------------------------------------
// Device scratch
// ---------------------------------------------------------------------------
__device__ float d_WihT0[CC * GG];
__device__ float d_WihT1[CC * GG];
__device__ float d_enc[BB * LL * CC];
__device__ float d_gi0[(long)BB * LL * GG];
__device__ float d_gi1[(long)BB * LL * GG];
// Wc bf16 hi/lo in 272B-padded rows: [part][c][136 bf16]
__device__ __nv_bfloat16 d_WcB[2][128 * 136];

// ---------------------------------------------------------------------------
// Setup: WihT transposes + Wc bf16 hi/lo padded tiles.
// ---------------------------------------------------------------------------
__global__ void k_setup(const float* __restrict__ Wc,
                        const float* __restrict__ Wih_f,
                        const float* __restrict__ Wih_b)
{
    const int i      = blockIdx.x * blockDim.x + threadIdx.x;
    const int stride = gridDim.x * blockDim.x;

    for (int idx = i; idx < CC * GG; idx += stride) {
        int k = idx / GG, g = idx % GG;
        d_WihT0[idx] = Wih_f[g * CC + k];
        d_WihT1[idx] = Wih_b[g * CC + k];
    }
    for (int idx = i; idx < 128 * 128; idx += stride) {
        int c = idx >> 7, k = idx & 127;
        float x = Wc[c * EE + k];
        __nv_bfloat16 hi = __float2bfloat16_rn(x);
        __nv_bfloat16 lo = __float2bfloat16_rn(x - __bfloat162float(hi));
        d_WcB[0][c * 136 + k] = hi;
        d_WcB[1][c * 136 + k] = lo;
    }
}

// ---------------------------------------------------------------------------
// K1 v5: tree encoder on tensor cores via legacy mma.sync (bf16 hi/lo x3).
// One CTA = two (b,l) positions. A[128 rows][K=128] gathered emb (rows 63,
// 127 zero-padded), B = Wc[c][k] (row-major [N][K] == col-major B). 8 warps,
// warp w owns M rows [16w,16w+16) x full N=128 (fp32 acc, 16 n8-tiles).
// smem rows padded to 272B (17 x 16B -> ldmatrix conflict-free).
// Epilogue: acc -> 129-stride f32 staging (overlays A) -> heap/max/relu.
// ---------------------------------------------------------------------------
#define K1_TKS 0
#define K1_BCS 512
#define K1_AHI 1024
#define K1_ALO 35840
#define K1_BHI 70656
#define K1_BLO 105472
#define K1_STG 1024
#define K1_SMEM_BYTES 140288

__global__ void __launch_bounds__(256) k_tree_encode(const int* __restrict__ tokens,
                                                     const float* __restrict__ emb,
                                                     const float* __restrict__ bc)
{
    extern __shared__ char smem[];
    const uint32_t sb = smem_u32(smem);
    const int tid  = threadIdx.x;
    const int wid  = tid >> 5;
    const int lane = tid & 31;

    int*   tks = (int*)(smem + K1_TKS);
    float* bcs = (float*)(smem + K1_BCS);

    const int bl0 = blockIdx.x * 2;
    if (tid < 2 * TT) tks[tid] = tokens[bl0 * TT + tid];
    if (tid < CC)     bcs[tid] = bc[tid];

    // copy Wc hi/lo padded tiles (69632B) linearly into smem B region
    {
        const float4* bsrc = (const float4*)d_WcB;
        float4*       bdst = (float4*)(smem + K1_BHI);
        for (int i = tid; i < 4352; i += 256) bdst[i] = bsrc[i];
    }
    __syncthreads();   // tks visible

    // A gather + hi/lo convert. chunk = (row m, 16B piece j)
    for (int ci = tid; ci < 2048; ci += 256) {
        const int m = ci >> 4;
        const int j = ci & 15;
        const int g = m >> 6;
        const int t = m & 63;

        uint4* hip = (uint4*)(smem + K1_AHI + m * 272 + j * 16);
        uint4* lop = (uint4*)(smem + K1_ALO + m * 272 + j * 16);

        if (t == TT) {
            uint4 z = make_uint4(0u, 0u, 0u, 0u);
            *hip = z; *lop = z;
        } else {
            const float* src = &emb[(long)tks[g * TT + t] * EE + j * 8];
            float v[8];
            float4 x0 = *(const float4*)src;
            float4 x1 = *(const float4*)(src + 4);
            v[0]=x0.x; v[1]=x0.y; v[2]=x0.z; v[3]=x0.w;
            v[4]=x1.x; v[5]=x1.y; v[6]=x1.z; v[7]=x1.w;
            unsigned short h[8], l[8];
            #pragma unroll
            for (int i = 0; i < 8; i++) {
                __nv_bfloat16 hb = __float2bfloat16_rn(v[i]);
                __nv_bfloat16 lb = __float2bfloat16_rn(v[i] - __bfloat162float(hb));
                h[i] = __bfloat16_as_ushort(hb);
                l[i] = __bfloat16_as_ushort(lb);
            }
            uint4 uh, ul;
            uh.x = (uint32_t)h[0] | ((uint32_t)h[1] << 16);
            uh.y = (uint32_t)h[2] | ((uint32_t)h[3] << 16);
            uh.z = (uint32_t)h[4] | ((uint32_t)h[5] << 16);
            uh.w = (uint32_t)h[6] | ((uint32_t)h[7] << 16);
            ul.x = (uint32_t)l[0] | ((uint32_t)l[1] << 16);
            ul.y = (uint32_t)l[2] | ((uint32_t)l[3] << 16);
            ul.z = (uint32_t)l[4] | ((uint32_t)l[5] << 16);
            ul.w = (uint32_t)l[6] | ((uint32_t)l[7] << 16);
            *hip = uh; *lop = ul;
        }
    }
    __syncthreads();

    // MMA: warp w -> rows [16w, 16w+16), 16 n8 accumulator tiles
    float acc[16][4];
    #pragma unroll
    for (int i = 0; i < 16; i++) {
        acc[i][0] = 0.f; acc[i][1] = 0.f; acc[i][2] = 0.f; acc[i][3] = 0.f;
    }

    // per-lane ldmatrix row addressing: lane&15 -> row, lane>>4 -> k-half 16B
    const uint32_t arow = (uint32_t)(16 * wid + (lane & 15)) * 272 + ((lane >> 4) << 4);
    const uint32_t brow = (uint32_t)(lane & 15) * 272 + ((lane >> 4) << 4);

    const uint32_t AOFF[3] = { K1_AHI, K1_AHI, K1_ALO };
    const uint32_t BOFF[3] = { K1_BHI, K1_BLO, K1_BHI };

    #pragma unroll
    for (int p = 0; p < 3; p++) {
        const uint32_t abase = sb + AOFF[p] + arow;
        const uint32_t bbase = sb + BOFF[p] + brow;
        #pragma unroll
        for (int kk = 0; kk < 8; kk++) {
            uint32_t a0, a1, a2, a3;
            ldsm_x4(a0, a1, a2, a3, abase + kk * 32);
            #pragma unroll
            for (int nt = 0; nt < 8; nt++) {
                uint32_t b0, b1, b2, b3;
                ldsm_x4(b0, b1, b2, b3, bbase + (uint32_t)(nt * 16) * 272 + kk * 32);
                hmma(acc[2*nt][0], acc[2*nt][1], acc[2*nt][2], acc[2*nt][3],
                     a0, a1, a2, a3, b0, b2);
                hmma(acc[2*nt+1][0], acc[2*nt+1][1], acc[2*nt+1][2], acc[2*nt+1][3],
                     a0, a1, a2, a3, b1, b3);
            }
        }
    }
    __syncthreads();   // all HMMA smem reads done before overlaying A

    // acc -> staging (f32, row stride 129)
    float* stg = (float*)(smem + K1_STG);
    {
        const int mrow = 16 * wid + (lane >> 2);       // rows mrow and mrow+8
        const int ncol = (lane & 3) * 2;
        #pragma unroll
        for (int nt = 0; nt < 16; nt++) {
            const int n0 = nt * 8 + ncol;
            stg[mrow * 129 + n0]           = acc[nt][0];
            stg[mrow * 129 + n0 + 1]       = acc[nt][1];
            stg[(mrow + 8) * 129 + n0]     = acc[nt][2];
            stg[(mrow + 8) * 129 + n0 + 1] = acc[nt][3];
        }
    }
    __syncthreads();

    // heap accumulate + bc + max + relu. thread = (g = tid>>7, c = tid&127)
    {
        const int g = tid >> 7;
        const int c = tid & 127;
        const float bcv = bcs[c];
        float* S = stg + (g * 64) * 129 + c;
        float mx = -3.0e38f;
        #pragma unroll
        for (int t = TT - 1; t >= 31; t--) {
            float v = S[t * 129] + bcv;
            S[t * 129] = v;
            mx = fmaxf(mx, v);
        }
        #pragma unroll
        for (int t = 30; t >= 0; t--) {
            float v = S[t * 129] + bcv + S[(2 * t + 1) * 129] + S[(2 * t + 2) * 129];
            S[t * 129] = v;
            mx = fmaxf(mx, v);
        }
        d_enc[(bl0 + g) * CC + c] = fmaxf(mx, 0.f);
    }
}

// ---------------------------------------------------------------------------
// K2: gi[d] = enc @ Wih[d]^T + bih[d]  (unchanged)
// ---------------------------------------------------------------------------
#define K2_WS 0
#define K2_ES 16384
#define K2_BI 24576
#define K2_SMEM_FLOATS 24704

__global__ void __launch_bounds__(256, 2) k_gi(const float* __restrict__ bih_f,
                                               const float* __restrict__ bih_b)
{
    extern __shared__ float sm[];
    float* ws  = sm + K2_WS;
    float* es  = sm + K2_ES;
    float* bis = sm + K2_BI;

    const int mt = blockIdx.x;
    const int nt = blockIdx.y;
    const int d  = blockIdx.z;
    const int m0 = mt * 64;
    const int g0 = nt * 128;
    const int tid = threadIdx.x;

    const float* WT  = d ? d_WihT1 : d_WihT0;
    const float* bih = d ? bih_b   : bih_f;
    float*       gi  = d ? d_gi1   : d_gi0;

    for (int idx = tid; idx < (128 * 128) / 4; idx += 256) {
        int k  = idx >> 5;
        int j4 = (idx & 31) << 2;
        float4 v = *(const float4*)&WT[k * GG + g0 + j4];
        *(float4*)&ws[k * 128 + j4] = v;
    }
    for (int idx = tid; idx < (64 * 128) / 4; idx += 256) {
        int i  = idx >> 5;
        int k4 = (idx & 31) << 2;
        float4 v = *(const float4*)&d_enc[(m0 + i) * CC + k4];
        *(float4*)&es[i * 128 + k4] = v;
    }
    if (tid < 128) bis[tid] = bih[g0 + tid];
    __syncthreads();

    const int w     = tid >> 5;
    const int lane  = tid & 31;
    const int c4    = lane << 2;
    const int ibase = w * 8;

    unsigned long long acc2[8][2];
    #pragma unroll
    for (int n = 0; n < 8; n++) { acc2[n][0] = 0ull; acc2[n][1] = 0ull; }

    for (int k = 0; k < CC; k += 4) {
        ulonglong2 wu[4];
        #pragma unroll
        for (int kk = 0; kk < 4; kk++)
            wu[kk] = *(const ulonglong2*)&ws[(k + kk) * 128 + c4];

        #pragma unroll
        for (int g = 0; g < 2; g++) {
            float4 e4[4];
            #pragma unroll
            for (int n = 0; n < 4; n++)
                e4[n] = *(float4*)&es[(ibase + g * 4 + n) * 128 + k];
            #pragma unroll
            for (int kk = 0; kk < 4; kk++) {
                #pragma unroll
                for (int n = 0; n < 4; n++) {
                    float ev = (kk == 0) ? e4[n].x : (kk == 1) ? e4[n].y
                             : (kk == 2) ? e4[n].z : e4[n].w;
                    unsigned long long eb = pk2(ev);
                    acc2[g * 4 + n][0] = fma2(eb, wu[kk].x, acc2[g * 4 + n][0]);
                    acc2[g * 4 + n][1] = fma2(eb, wu[kk].y, acc2[g * 4 + n][1]);
                }
            }
        }
    }

    float4 bv = *(float4*)&bis[c4];
    #pragma unroll
    for (int n = 0; n < 8; n++) {
        float2 lo = upk(acc2[n][0]);
        float2 hi = upk(acc2[n][1]);
        float4 r;
        r.x = lo.x + bv.x;
        r.y = lo.y + bv.y;
        r.z = hi.x + bv.z;
        r.w = hi.y + bv.w;
        *(float4*)&gi[(long)(m0 + ibase + n) * GG + g0 + c4] = r;
    }
}

// ---------------------------------------------------------------------------
// K3: cluster-local bidirectional GRU — exact R5 version (203us known-good).
// ---------------------------------------------------------------------------
__device__ __forceinline__ void st_cluster_f32(uint32_t local_addr, uint32_t rank, float v) {
    asm volatile(
        "{\n\t"
        ".reg .b32 r;\n\t"
        "mapa.shared::cluster.u32 r, %0, %1;\n\t"
        "st.shared::cluster.f32 [r], %2;\n\t"
        "}"
        :: "r"(local_addr), "r"(rank), "f"(v) : "memory");
}

__global__ void __launch_bounds__(384, 1) __cluster_dims__(4, 1, 1)
k_gru(const float* __restrict__ Whh_f, const float* __restrict__ bhh_f,
      const float* __restrict__ Whh_b, const float* __restrict__ bhh_b,
      float* __restrict__ out)
{
    __shared__ float hbuf[2][2][HH];     // [buf][bt][unit]
    __shared__ float part[2][2][192];    // [half][bt][row] partial dots

    const int tid = threadIdx.x;
    uint32_t cr;
    asm("mov.u32 %0, %%cluster_ctarank;" : "=r"(cr));

    const int cid = blockIdx.x >> 2;
    const int d   = cid >> 4;
    const int bp  = cid & 15;
    const int U0  = (int)cr << 6;

    const float* Whh = d ? Whh_b : Whh_f;
    const float* bhh = d ? bhh_b : bhh_f;
    const float* gi  = d ? d_gi1 : d_gi0;

    const int w    = tid >> 5;
    const int lane = tid & 31;
    const int rw   = (w % 6) * 32 + lane;  // 0..191  (gate*64 + u)
    const int half = w / 6;                // 0 or 1

    const int gate = rw >> 6, uu = rw & 63;
    float4 wreg[32];
    {
        const float* wrow = &Whh[(gate * HH + U0 + uu) * HH + half * 128];
        #pragma unroll
        for (int i = 0; i < 32; i++) wreg[i] = *(const float4*)&wrow[i * 4];
    }

    const int u_f   = tid & 63;
    const int bt_f  = tid >> 6;
    const int bglob = bp * 2 + bt_f;
    float br = 0.f, bz = 0.f, bn = 0.f;
    uint32_t haddr0 = 0, haddr1 = 0;
    if (tid < 128) {
        br = bhh[U0 + u_f];
        bz = bhh[HH + U0 + u_f];
        bn = bhh[2 * HH + U0 + u_f];
        haddr0 = smem_u32(&hbuf[0][bt_f][U0 + u_f]);
        haddr1 = smem_u32(&hbuf[1][bt_f][U0 + u_f]);
    }

    for (int i = tid; i < 2 * HH; i += 384) hbuf[0][i >> 8][i & 255] = 0.f;

    float mx = -3.0e38f;

    asm volatile("barrier.cluster.arrive.aligned;" ::: "memory");
    asm volatile("barrier.cluster.wait.aligned;"   ::: "memory");

    for (int st = 0; st < LL; st++) {
        const int p = st & 1;
        const int t = d ? (LL - 1 - st) : st;

        float gir = 0.f, giz = 0.f, gin = 0.f;
        if (tid < 128) {
            const long gb = ((long)bglob * LL + t) * GG + U0 + u_f;
            gir = __ldg(&gi[gb]);
            giz = __ldg(&gi[gb + HH]);
            gin = __ldg(&gi[gb + 2 * HH]);
        }

        float4 a0 = make_float4(0.f, 0.f, 0.f, 0.f);
        float4 a1 = make_float4(0.f, 0.f, 0.f, 0.f);
        {
            const float* h0 = &hbuf[p][0][half * 128];
            const float* h1 = &hbuf[p][1][half * 128];
            #pragma unroll
            for (int i = 0; i < 32; i++) {
                float4 wv = wreg[i];
                float4 x0 = *(const float4*)&h0[i * 4];
                float4 x1 = *(const float4*)&h1[i * 4];
                a0.x += wv.x * x0.x; a0.y += wv.y * x0.y;
                a0.z += wv.z * x0.z; a0.w += wv.w * x0.w;
                a1.x += wv.x * x1.x; a1.y += wv.y * x1.y;
                a1.z += wv.z * x1.z; a1.w += wv.w * x1.w;
            }
        }
        const float s0 = (a0.x + a0.y) + (a0.z + a0.w);
        const float s1 = (a1.x + a1.y) + (a1.z + a1.w);

        part[half][0][rw] = s0;
        part[half][1][rw] = s1;
        __syncthreads();

        if (tid < 128) {
            const float gr = part[0][bt_f][u_f]       + part[1][bt_f][u_f];
            const float gz = part[0][bt_f][64 + u_f]  + part[1][bt_f][64 + u_f];
            const float gn = part[0][bt_f][128 + u_f] + part[1][bt_f][128 + u_f];
            const float hp = hbuf[p][bt_f][U0 + u_f];

            const float r  = 1.f / (1.f + __expf(-(gir + gr + br)));
            const float z  = 1.f / (1.f + __expf(-(giz + gz + bz)));
            const float nn = tanhf(gin + r * (gn + bn));
            const float hn = (1.f - z) * nn + z * hp;
            mx = fmaxf(mx, hn);

            hbuf[p ^ 1][bt_f][U0 + u_f] = hn;
            const uint32_t ha = (p ^ 1) ? haddr1 : haddr0;
            #pragma unroll
            for (uint32_t rk = 0; rk < 4; rk++) {
                if (rk != cr) st_cluster_f32(ha, rk, hn);
            }
        }

        asm volatile("barrier.cluster.arrive.aligned;" ::: "memory");
        asm volatile("barrier.cluster.wait.aligned;"   ::: "memory");
    }

    if (tid < 128) out[bglob * 512 + d * 256 + U0 + u_f] = mx;
}

// ---------------------------------------------------------------------------
// kernel_launch
// ---------------------------------------------------------------------------
extern "C" void kernel_launch(void* const* d_in, const int* in_sizes, int n_in,
                              void* d_out, int out_size)
{
    const int*   tokens = (const int*)  d_in[0];
    const float* emb    = (const float*)d_in[1];
    const float* Wc     = (const float*)d_in[2];
    const float* bc     = (const float*)d_in[3];
    const float* Wih_f  = (const float*)d_in[4];
    const float* Whh_f  = (const float*)d_in[5];
    const float* bih_f  = (const float*)d_in[6];
    const float* bhh_f  = (const float*)d_in[7];
    const float* Wih_b  = (const float*)d_in[8];
    const float* Whh_b  = (const float*)d_in[9];
    const float* bih_b  = (const float*)d_in[10];
    const float* bhh_b  = (const float*)d_in[11];
    float* out = (float*)d_out;

    const int SM2 = K2_SMEM_FLOATS * 4;

    cudaFuncSetAttribute(k_tree_encode, cudaFuncAttributeMaxDynamicSharedMemorySize, K1_SMEM_BYTES);
    cudaFuncSetAttribute(k_gi,          cudaFuncAttributeMaxDynamicSharedMemorySize, SM2);

    k_setup<<<128, 256>>>(Wc, Wih_f, Wih_b);
    k_tree_encode<<<BB * LL / 2, 256, K1_SMEM_BYTES>>>(tokens, emb, bc);
    dim3 g2(64, 6, 2);
    k_gi<<<g2, 256, SM2>>>(bih_f, bih_b);
    k_gru<<<128, 384>>>(Whh_f, bhh_f, Whh_b, bhh_b, out);
}

// round 9
// speedup vs baseline: 1.6715x; 1.6715x over previous
#include <cuda_runtime.h>
#include <cuda_bf16.h>
#include <cstdint>

// Problem constants (fixed by the dataset)
#define BB 32      // batch
#define LL 128     // sequence length
#define TT 63      // tree nodes (2^6 - 1)
#define EE 128     // embedding dim
#define CC 128     // conv/encoder channels
#define HH 256     // GRU hidden
#define GG 768     // 3*H gate columns
#define VV 50000   // vocab

// ---------------------------------------------------------------------------
// f32x2 helpers (issue-rate neutral on this chip, but compact)
// ---------------------------------------------------------------------------
__device__ __forceinline__ unsigned long long fma2(unsigned long long a,
                                                   unsigned long long b,
                                                   unsigned long long c) {
    unsigned long long d;
    asm("fma.rn.f32x2 %0, %1, %2, %3;" : "=l"(d) : "l"(a), "l"(b), "l"(c));
    return d;
}
__device__ __forceinline__ unsigned long long pk2(float v) {
    unsigned long long r;
    asm("mov.b64 %0, {%1, %1};" : "=l"(r) : "f"(v));
    return r;
}
__device__ __forceinline__ float2 upk(unsigned long long v) {
    float2 f;
    asm("mov.b64 {%0, %1}, %2;" : "=f"(f.x), "=f"(f.y) : "l"(v));
    return f;
}
__device__ __forceinline__ uint32_t smem_u32(const void* p) {
    uint32_t a;
    asm("{ .reg .u64 t; cvta.to.shared.u64 t, %1; cvt.u32.u64 %0, t; }"
        : "=r"(a) : "l"(p));
    return a;
}

// ---------------------------------------------------------------------------
// Device scratch (static only)
// ---------------------------------------------------------------------------
__device__ float d_WcT[EE * CC];            // [k][c]
__device__ float d_WihT0[CC * GG];          // [k][g]
__device__ float d_WihT1[CC * GG];
__device__ float d_P[(long)VV * CC];        // projected vocab: P[v][c]
__device__ float d_enc[BB * LL * CC];
__device__ float d_gi0[(long)BB * LL * GG];
__device__ float d_gi1[(long)BB * LL * GG];

// ---------------------------------------------------------------------------
// Setup: transposes.
// ---------------------------------------------------------------------------
__global__ void k_setup(const float* __restrict__ Wc,
                        const float* __restrict__ Wih_f,
                        const float* __restrict__ Wih_b)
{
    const int i      = blockIdx.x * blockDim.x + threadIdx.x;
    const int stride = gridDim.x * blockDim.x;

    for (int idx = i; idx < EE * CC; idx += stride) {
        int e = idx / CC, c = idx % CC;
        d_WcT[e * CC + c] = Wc[c * EE + e];
    }
    for (int idx = i; idx < CC * GG; idx += stride) {
        int k = idx / GG, g = idx % GG;
        d_WihT0[idx] = Wih_f[g * CC + k];
        d_WihT1[idx] = Wih_b[g * CC + k];
    }
}

// ---------------------------------------------------------------------------
// KV: projected-vocab table  P[v] = Wc @ emb[v]   (the FLOP-cut enabler)
// Tile: 64 vocab rows x 128 channels, K=128. Same proven structure as K2.
// Grid: ceil(50000/64) = 782.
// ---------------------------------------------------------------------------
#define KV_WS 0
#define KV_ES 16384
#define KV_SMEM_FLOATS 24576

__global__ void __launch_bounds__(256, 2) k_vocab(const float* __restrict__ emb)
{
    extern __shared__ float sm[];
    float* ws = sm + KV_WS;   // WcT [k][c] 128x128
    float* es = sm + KV_ES;   // emb rows [64][128]

    const int m0  = blockIdx.x * 64;
    const int tid = threadIdx.x;

    for (int idx = tid; idx < (128 * 128) / 4; idx += 256)
        ((float4*)ws)[idx] = ((const float4*)d_WcT)[idx];
    for (int idx = tid; idx < (64 * 128) / 4; idx += 256) {
        int i  = idx >> 5;
        int k4 = (idx & 31) << 2;
        float4 v = make_float4(0.f, 0.f, 0.f, 0.f);
        if (m0 + i < VV) v = *(const float4*)&emb[(long)(m0 + i) * EE + k4];
        *(float4*)&es[i * 128 + k4] = v;
    }
    __syncthreads();

    const int w     = tid >> 5;
    const int lane  = tid & 31;
    const int c4    = lane << 2;
    const int ibase = w * 8;

    unsigned long long acc2[8][2];
    #pragma unroll
    for (int n = 0; n < 8; n++) { acc2[n][0] = 0ull; acc2[n][1] = 0ull; }

    for (int k = 0; k < EE; k += 4) {
        ulonglong2 wu[4];
        #pragma unroll
        for (int kk = 0; kk < 4; kk++)
            wu[kk] = *(const ulonglong2*)&ws[(k + kk) * 128 + c4];

        #pragma unroll
        for (int g = 0; g < 2; g++) {
            float4 e4[4];
            #pragma unroll
            for (int n = 0; n < 4; n++)
                e4[n] = *(float4*)&es[(ibase + g * 4 + n) * 128 + k];
            #pragma unroll
            for (int kk = 0; kk < 4; kk++) {
                #pragma unroll
                for (int n = 0; n < 4; n++) {
                    float ev = (kk == 0) ? e4[n].x : (kk == 1) ? e4[n].y
                             : (kk == 2) ? e4[n].z : e4[n].w;
                    unsigned long long eb = pk2(ev);
                    acc2[g * 4 + n][0] = fma2(eb, wu[kk].x, acc2[g * 4 + n][0]);
                    acc2[g * 4 + n][1] = fma2(eb, wu[kk].y, acc2[g * 4 + n][1]);
                }
            }
        }
    }

    #pragma unroll
    for (int n = 0; n < 8; n++) {
        const int row = m0 + ibase + n;
        if (row < VV) {
            float2 lo = upk(acc2[n][0]);
            float2 hi = upk(acc2[n][1]);
            float4 r = make_float4(lo.x, lo.y, hi.x, hi.y);
            *(float4*)&d_P[(long)row * CC + c4] = r;
        }
    }
}

// ---------------------------------------------------------------------------
// KT: tree encoder = gather P[tok] + bc, heap accumulate, max, relu.
// One CTA = 2 (b,l) positions, 256 threads. No GEMM.
// smem: stg [2][64][128] f32 (node rows; row 63 of each unused),
//       bcs [128], tks [128 ints]. ~66KB -> 3 CTAs/SM.
// ---------------------------------------------------------------------------
#define KT_STG 0
#define KT_BCS 16384
#define KT_TKS 16512
#define KT_SMEM_FLOATS 16672

__global__ void __launch_bounds__(256) k_tree(const int* __restrict__ tokens,
                                              const float* __restrict__ bc)
{
    extern __shared__ float sm[];
    float* stg = sm + KT_STG;
    float* bcs = sm + KT_BCS;
    int*   tks = (int*)(sm + KT_TKS);

    const int bl0 = blockIdx.x * 2;
    const int tid = threadIdx.x;

    if (tid < 2 * TT) tks[tid] = tokens[bl0 * TT + tid];
    if (tid < CC)     bcs[tid] = bc[tid];
    __syncthreads();

    // gather: 126 P-rows x 32 float4. Warp = one 512B row -> fully coalesced.
    const float4* P4 = (const float4*)d_P;
    for (int ci = tid; ci < 126 * 32; ci += 256) {
        const int tl = ci >> 5;            // 0..125
        const int j  = ci & 31;
        const int g  = (tl >= TT) ? 1 : 0;
        const int t  = tl - g * TT;
        float4 v = __ldg(&P4[(long)tks[tl] * 32 + j]);
        float4 b = *(const float4*)&bcs[j * 4];
        v.x += b.x; v.y += b.y; v.z += b.z; v.w += b.w;
        *(float4*)&stg[(g * 64 + t) * 128 + j * 4] = v;
    }
    __syncthreads();

    // heap accumulate + max + relu. thread = (g = tid>>7, c = tid&127)
    {
        const int g = tid >> 7;
        const int c = tid & 127;
        float* S = stg + (g * 64) * 128 + c;
        float mx = -3.0e38f;
        #pragma unroll
        for (int t = TT - 1; t >= 31; t--) mx = fmaxf(mx, S[t * 128]);
        #pragma unroll
        for (int t = 30; t >= 0; t--) {
            float v = S[t * 128] + S[(2 * t + 1) * 128] + S[(2 * t + 2) * 128];
            S[t * 128] = v;
            mx = fmaxf(mx, v);
        }
        d_enc[(bl0 + g) * CC + c] = fmaxf(mx, 0.f);
    }
}

// ---------------------------------------------------------------------------
// K2: gi[d] = enc @ Wih[d]^T + bih[d]  (proven R6 version, unchanged)
// ---------------------------------------------------------------------------
#define K2_WS 0
#define K2_ES 16384
#define K2_BI 24576
#define K2_SMEM_FLOATS 24704

__global__ void __launch_bounds__(256, 2) k_gi(const float* __restrict__ bih_f,
                                               const float* __restrict__ bih_b)
{
    extern __shared__ float sm[];
    float* ws  = sm + K2_WS;
    float* es  = sm + K2_ES;
    float* bis = sm + K2_BI;

    const int mt = blockIdx.x;
    const int nt = blockIdx.y;
    const int d  = blockIdx.z;
    const int m0 = mt * 64;
    const int g0 = nt * 128;
    const int tid = threadIdx.x;

    const float* WT  = d ? d_WihT1 : d_WihT0;
    const float* bih = d ? bih_b   : bih_f;
    float*       gi  = d ? d_gi1   : d_gi0;

    for (int idx = tid; idx < (128 * 128) / 4; idx += 256) {
        int k  = idx >> 5;
        int j4 = (idx & 31) << 2;
        float4 v = *(const float4*)&WT[k * GG + g0 + j4];
        *(float4*)&ws[k * 128 + j4] = v;
    }
    for (int idx = tid; idx < (64 * 128) / 4; idx += 256) {
        int i  = idx >> 5;
        int k4 = (idx & 31) << 2;
        float4 v = *(const float4*)&d_enc[(m0 + i) * CC + k4];
        *(float4*)&es[i * 128 + k4] = v;
    }
    if (tid < 128) bis[tid] = bih[g0 + tid];
    __syncthreads();

    const int w     = tid >> 5;
    const int lane  = tid & 31;
    const int c4    = lane << 2;
    const int ibase = w * 8;

    unsigned long long acc2[8][2];
    #pragma unroll
    for (int n = 0; n < 8; n++) { acc2[n][0] = 0ull; acc2[n][1] = 0ull; }

    for (int k = 0; k < CC; k += 4) {
        ulonglong2 wu[4];
        #pragma unroll
        for (int kk = 0; kk < 4; kk++)
            wu[kk] = *(const ulonglong2*)&ws[(k + kk) * 128 + c4];

        #pragma unroll
        for (int g = 0; g < 2; g++) {
            float4 e4[4];
            #pragma unroll
            for (int n = 0; n < 4; n++)
                e4[n] = *(float4*)&es[(ibase + g * 4 + n) * 128 + k];
            #pragma unroll
            for (int kk = 0; kk < 4; kk++) {
                #pragma unroll
                for (int n = 0; n < 4; n++) {
                    float ev = (kk == 0) ? e4[n].x : (kk == 1) ? e4[n].y
                             : (kk == 2) ? e4[n].z : e4[n].w;
                    unsigned long long eb = pk2(ev);
                    acc2[g * 4 + n][0] = fma2(eb, wu[kk].x, acc2[g * 4 + n][0]);
                    acc2[g * 4 + n][1] = fma2(eb, wu[kk].y, acc2[g * 4 + n][1]);
                }
            }
        }
    }

    float4 bv = *(float4*)&bis[c4];
    #pragma unroll
    for (int n = 0; n < 8; n++) {
        float2 lo = upk(acc2[n][0]);
        float2 hi = upk(acc2[n][1]);
        float4 r;
        r.x = lo.x + bv.x;
        r.y = lo.y + bv.y;
        r.z = hi.x + bv.z;
        r.w = hi.y + bv.w;
        *(float4*)&gi[(long)(m0 + ibase + n) * GG + g0 + c4] = r;
    }
}

// ---------------------------------------------------------------------------
// K3: cluster-local bidirectional GRU — exact R5 version (~200us known-good).
// ---------------------------------------------------------------------------
__device__ __forceinline__ void st_cluster_f32(uint32_t local_addr, uint32_t rank, float v) {
    asm volatile(
        "{\n\t"
        ".reg .b32 r;\n\t"
        "mapa.shared::cluster.u32 r, %0, %1;\n\t"
        "st.shared::cluster.f32 [r], %2;\n\t"
        "}"
        :: "r"(local_addr), "r"(rank), "f"(v) : "memory");
}

__global__ void __launch_bounds__(384, 1) __cluster_dims__(4, 1, 1)
k_gru(const float* __restrict__ Whh_f, const float* __restrict__ bhh_f,
      const float* __restrict__ Whh_b, const float* __restrict__ bhh_b,
      float* __restrict__ out)
{
    __shared__ float hbuf[2][2][HH];     // [buf][bt][unit]
    __shared__ float part[2][2][192];    // [half][bt][row] partial dots

    const int tid = threadIdx.x;
    uint32_t cr;
    asm("mov.u32 %0, %%cluster_ctarank;" : "=r"(cr));

    const int cid = blockIdx.x >> 2;
    const int d   = cid >> 4;
    const int bp  = cid & 15;
    const int U0  = (int)cr << 6;

    const float* Whh = d ? Whh_b : Whh_f;
    const float* bhh = d ? bhh_b : bhh_f;
    const float* gi  = d ? d_gi1 : d_gi0;

    const int w    = tid >> 5;
    const int lane = tid & 31;
    const int rw   = (w % 6) * 32 + lane;  // 0..191  (gate*64 + u)
    const int half = w / 6;                // 0 or 1

    const int gate = rw >> 6, uu = rw & 63;
    float4 wreg[32];
    {
        const float* wrow = &Whh[(gate * HH + U0 + uu) * HH + half * 128];
        #pragma unroll
        for (int i = 0; i < 32; i++) wreg[i] = *(const float4*)&wrow[i * 4];
    }

    const int u_f   = tid & 63;
    const int bt_f  = tid >> 6;
    const int bglob = bp * 2 + bt_f;
    float br = 0.f, bz = 0.f, bn = 0.f;
    uint32_t haddr0 = 0, haddr1 = 0;
    if (tid < 128) {
        br = bhh[U0 + u_f];
        bz = bhh[HH + U0 + u_f];
        bn = bhh[2 * HH + U0 + u_f];
        haddr0 = smem_u32(&hbuf[0][bt_f][U0 + u_f]);
        haddr1 = smem_u32(&hbuf[1][bt_f][U0 + u_f]);
    }

    for (int i = tid; i < 2 * HH; i += 384) hbuf[0][i >> 8][i & 255] = 0.f;

    float mx = -3.0e38f;

    asm volatile("barrier.cluster.arrive.aligned;" ::: "memory");
    asm volatile("barrier.cluster.wait.aligned;"   ::: "memory");

    for (int st = 0; st < LL; st++) {
        const int p = st & 1;
        const int t = d ? (LL - 1 - st) : st;

        float gir = 0.f, giz = 0.f, gin = 0.f;
        if (tid < 128) {
            const long gb = ((long)bglob * LL + t) * GG + U0 + u_f;
            gir = __ldg(&gi[gb]);
            giz = __ldg(&gi[gb + HH]);
            gin = __ldg(&gi[gb + 2 * HH]);
        }

        float4 a0 = make_float4(0.f, 0.f, 0.f, 0.f);
        float4 a1 = make_float4(0.f, 0.f, 0.f, 0.f);
        {
            const float* h0 = &hbuf[p][0][half * 128];
            const float* h1 = &hbuf[p][1][half * 128];
            #pragma unroll
            for (int i = 0; i < 32; i++) {
                float4 wv = wreg[i];
                float4 x0 = *(const float4*)&h0[i * 4];
                float4 x1 = *(const float4*)&h1[i * 4];
                a0.x += wv.x * x0.x; a0.y += wv.y * x0.y;
                a0.z += wv.z * x0.z; a0.w += wv.w * x0.w;
                a1.x += wv.x * x1.x; a1.y += wv.y * x1.y;
                a1.z += wv.z * x1.z; a1.w += wv.w * x1.w;
            }
        }
        const float s0 = (a0.x + a0.y) + (a0.z + a0.w);
        const float s1 = (a1.x + a1.y) + (a1.z + a1.w);

        part[half][0][rw] = s0;
        part[half][1][rw] = s1;
        __syncthreads();

        if (tid < 128) {
            const float gr = part[0][bt_f][u_f]       + part[1][bt_f][u_f];
            const float gz = part[0][bt_f][64 + u_f]  + part[1][bt_f][64 + u_f];
            const float gn = part[0][bt_f][128 + u_f] + part[1][bt_f][128 + u_f];
            const float hp = hbuf[p][bt_f][U0 + u_f];

            const float r  = 1.f / (1.f + __expf(-(gir + gr + br)));
            const float z  = 1.f / (1.f + __expf(-(giz + gz + bz)));
            const float nn = tanhf(gin + r * (gn + bn));
            const float hn = (1.f - z) * nn + z * hp;
            mx = fmaxf(mx, hn);

            hbuf[p ^ 1][bt_f][U0 + u_f] = hn;
            const uint32_t ha = (p ^ 1) ? haddr1 : haddr0;
            #pragma unroll
            for (uint32_t rk = 0; rk < 4; rk++) {
                if (rk != cr) st_cluster_f32(ha, rk, hn);
            }
        }

        asm volatile("barrier.cluster.arrive.aligned;" ::: "memory");
        asm volatile("barrier.cluster.wait.aligned;"   ::: "memory");
    }

    if (tid < 128) out[bglob * 512 + d * 256 + U0 + u_f] = mx;
}

// ---------------------------------------------------------------------------
// kernel_launch
// ---------------------------------------------------------------------------
extern "C" void kernel_launch(void* const* d_in, const int* in_sizes, int n_in,
                              void* d_out, int out_size)
{
    const int*   tokens = (const int*)  d_in[0];
    const float* emb    = (const float*)d_in[1];
    const float* Wc     = (const float*)d_in[2];
    const float* bc     = (const float*)d_in[3];
    const float* Wih_f  = (const float*)d_in[4];
    const float* Whh_f  = (const float*)d_in[5];
    const float* bih_f  = (const float*)d_in[6];
    const float* bhh_f  = (const float*)d_in[7];
    const float* Wih_b  = (const float*)d_in[8];
    const float* Whh_b  = (const float*)d_in[9];
    const float* bih_b  = (const float*)d_in[10];
    const float* bhh_b  = (const float*)d_in[11];
    float* out = (float*)d_out;

    const int SMV = KV_SMEM_FLOATS * 4;
    const int SMT = KT_SMEM_FLOATS * 4;
    const int SM2 = K2_SMEM_FLOATS * 4;

    cudaFuncSetAttribute(k_vocab, cudaFuncAttributeMaxDynamicSharedMemorySize, SMV);
    cudaFuncSetAttribute(k_tree,  cudaFuncAttributeMaxDynamicSharedMemorySize, SMT);
    cudaFuncSetAttribute(k_gi,    cudaFuncAttributeMaxDynamicSharedMemorySize, SM2);

    k_setup<<<128, 256>>>(Wc, Wih_f, Wih_b);
    k_vocab<<<(VV + 63) / 64, 256, SMV>>>(emb);
    k_tree<<<BB * LL / 2, 256, SMT>>>(tokens, bc);
    dim3 g2(64, 6, 2);
    k_gi<<<g2, 256, SM2>>>(bih_f, bih_b);
    k_gru<<<128, 384>>>(Whh_f, bhh_f, Whh_b, bhh_b, out);
}